// round 2
// baseline (speedup 1.0000x reference)
#include <cuda_runtime.h>
#include <cuda_bf16.h>
#include <math.h>

// Spline_2817498546198
// rows = B*D = 2048, N = 4096 knots per row, Q = 2048 queries per row.
// One CTA per row. Natural cubic spline: tridiagonal solve for knot
// derivatives via chunked Thomas with warmup (valid because the system is
// strictly diagonally dominant -> recurrences contract geometrically,
// factor <= ~0.6/step, 0.6^32 ~ 8e-8), then branchless binary search +
// Hermite cubic eval for queries.

#define N_KNOTS 4096
#define QPTS    2048
#define CHUNK   16
#define WARM    32
#define NCHUNK  (N_KNOTS / CHUNK)   // 256
#define THREADS 256

__global__ __launch_bounds__(THREADS, 3)
void spline_kernel(const float* __restrict__ t_g,
                   const float* __restrict__ y_g,
                   const float* __restrict__ tq_g,
                   float* __restrict__ out_g)
{
    extern __shared__ float sm[];
    float* st = sm;               // t   [4096]
    float* sy = sm + N_KNOTS;     // y   [4096]
    float* sc = sm + 2 * N_KNOTS; // c   [4096]
    float* sd = sm + 3 * N_KNOTS; // d -> x [4096]

    const int row = blockIdx.x;
    const int tid = threadIdx.x;

    const float4* tg4 = (const float4*)(t_g + (size_t)row * N_KNOTS);
    const float4* yg4 = (const float4*)(y_g + (size_t)row * N_KNOTS);
    float4* st4 = (float4*)st;
    float4* sy4 = (float4*)sy;
    #pragma unroll
    for (int i = tid; i < N_KNOTS / 4; i += THREADS) {
        st4[i] = tg4[i];
        sy4[i] = yg4[i];
    }
    __syncthreads();

    // ---------------- forward Thomas (chunked, with warmup) ----------------
    {
        const int start  = tid * CHUNK;
        const int wstart = (start >= WARM) ? (start - WARM) : 0;

        float cp = 0.0f, dp = 0.0f;
        float t_i = st[wstart];
        float y_i = sy[wstart];
        float idt_m = 0.0f, dy_m = 0.0f;   // idt[i-1], dy[i-1]
        if (wstart > 0) {
            float t_im1 = st[wstart - 1];
            float y_im1 = sy[wstart - 1];
            idt_m = 1.0f / (t_i - t_im1);
            dy_m  = y_i - y_im1;
        }

        for (int i = wstart; i < start + CHUNK; ++i) {
            float idt_p = 0.0f, dy_p = 0.0f;
            float t_ip1 = t_i, y_ip1 = y_i;
            if (i < N_KNOTS - 1) {
                t_ip1 = st[i + 1];
                y_ip1 = sy[i + 1];
                idt_p = 1.0f / (t_ip1 - t_i);
                dy_p  = y_ip1 - y_i;
            }
            float l, m, u, b;
            if (i == 0) {
                l = 0.0f; m = 2.0f * idt_p; u = idt_p;
                b = 3.0f * dy_p * idt_p * idt_p;
            } else if (i == N_KNOTS - 1) {
                l = idt_m; m = 2.0f * idt_m; u = 0.0f;
                b = 3.0f * dy_m * idt_m * idt_m;
            } else {
                l = idt_m; m = 2.0f * (idt_m + idt_p); u = idt_p;
                b = 3.0f * (dy_m * idt_m * idt_m + dy_p * idt_p * idt_p);
            }
            float inv = 1.0f / (m - l * cp);
            cp = u * inv;
            dp = (b - l * dp) * inv;
            if (i >= start) {
                sc[i] = cp;
                sd[i] = dp;
            }
            idt_m = idt_p; dy_m = dy_p; t_i = t_ip1; y_i = y_ip1;
        }
    }
    __syncthreads();

    // ---------------- backward substitution (chunked, with warmup) ---------
    float xloc[CHUNK];
    {
        const int start = tid * CHUNK;
        float x = 0.0f;
        // warmup over [start+CHUNK, start+CHUNK+WARM) (clamped to N)
        int wtop = start + CHUNK + WARM;
        if (wtop > N_KNOTS) wtop = N_KNOTS;
        for (int i = wtop - 1; i >= start + CHUNK; --i) {
            x = sd[i] - sc[i] * x;
        }
        #pragma unroll
        for (int j = CHUNK - 1; j >= 0; --j) {
            x = sd[start + j] - sc[start + j] * x;
            xloc[j] = x;
        }
    }
    __syncthreads();
    {
        const int start = tid * CHUNK;
        #pragma unroll
        for (int j = 0; j < CHUNK; ++j) sd[start + j] = xloc[j];
    }
    __syncthreads();

    // ---------------- query evaluation ----------------
    const float* tqg = tq_g + (size_t)row * QPTS;
    float* outg      = out_g + (size_t)row * QPTS;

    #pragma unroll
    for (int q = tid; q < QPTS; q += THREADS) {
        const float tq = tqg[q];

        // branchless: largest i with st[i] <= tq (tq >= st[0] guaranteed)
        int base = 0;
        #pragma unroll
        for (int s = N_KNOTS / 2; s > 0; s >>= 1) {
            if (st[base + s] <= tq) base += s;
        }
        int idx = base;
        if (idx > N_KNOTS - 2) idx = N_KNOTS - 2;

        const float t0 = st[idx],   t1 = st[idx + 1];
        const float y0 = sy[idx],   y1 = sy[idx + 1];
        const float d0 = sd[idx],   d1 = sd[idx + 1];
        const float dt = t1 - t0;
        const float s  = (tq - t0) / dt;

        const float c1 = y0 + d0 * dt * (1.0f / 3.0f);
        const float c2 = y1 - d1 * dt * (1.0f / 3.0f);
        const float p0 = y0;
        const float p1 = 3.0f * (c1 - y0);
        const float p2 = 3.0f * (y0 - 2.0f * c1 + c2);
        const float p3 = -y0 + 3.0f * c1 - 3.0f * c2 + y1;

        outg[q] = ((p3 * s + p2) * s + p1) * s + p0;
    }
}

extern "C" void kernel_launch(void* const* d_in, const int* in_sizes, int n_in,
                              void* d_out, int out_size)
{
    const float* t  = (const float*)d_in[0];
    const float* y  = (const float*)d_in[1];
    const float* tq = (const float*)d_in[2];
    float* out = (float*)d_out;

    const int rows = out_size / QPTS;   // 2048
    const int smem = 4 * N_KNOTS * sizeof(float);  // 64 KB

    cudaFuncSetAttribute(spline_kernel,
                         cudaFuncAttributeMaxDynamicSharedMemorySize, smem);

    spline_kernel<<<rows, THREADS, smem>>>(t, y, tq, out);
}

// round 3
// speedup vs baseline: 2.6758x; 2.6758x over previous
#include <cuda_runtime.h>
#include <cuda_bf16.h>
#include <math.h>

// Spline_2817498546198 — R3
// rows = 2048, N = 4096 knots, Q = 2048 queries per row. One CTA per row.
// Chunked Thomas solve with 32-step warmup (diagonally dominant -> contraction),
// skewed smem layout (conflict-free strided access), interpolation-guessed
// binary search with guaranteed-correct fallback.

#define N_KNOTS 4096
#define QPTS    2048
#define CHUNK   16
#define WARM    32
#define THREADS 256
#define SKW(i)  ((i) + ((i) >> 4))
#define ASZ     (N_KNOTS + (N_KNOTS >> 4))   // 4352 floats per array

__global__ __launch_bounds__(THREADS, 3)
void spline_kernel(const float* __restrict__ t_g,
                   const float* __restrict__ y_g,
                   const float* __restrict__ tq_g,
                   float* __restrict__ out_g)
{
    extern __shared__ float sm[];
    float* st = sm;            // t   (skewed)
    float* sy = sm + ASZ;      // y   (skewed)
    float* sc = sm + 2 * ASZ;  // c   (skewed)
    float* sd = sm + 3 * ASZ;  // d -> x (skewed)

    const int row = blockIdx.x;
    const int tid = threadIdx.x;

    // ---- load t, y into skewed smem ----
    const float4* tg4 = (const float4*)(t_g + (size_t)row * N_KNOTS);
    const float4* yg4 = (const float4*)(y_g + (size_t)row * N_KNOTS);
    #pragma unroll
    for (int v = tid; v < N_KNOTS / 4; v += THREADS) {
        float4 tv = tg4[v];
        float4 yv = yg4[v];
        int i = v * 4;
        int p = SKW(i);           // 4 consecutive i stay in same 16-block
        st[p]     = tv.x; st[p + 1] = tv.y; st[p + 2] = tv.z; st[p + 3] = tv.w;
        sy[p]     = yv.x; sy[p + 1] = yv.y; sy[p + 2] = yv.z; sy[p + 3] = yv.w;
    }
    __syncthreads();

    // ---------------- forward Thomas (chunked, warmup) ----------------
    {
        const int start  = tid * CHUNK;
        const int wstart = (start >= WARM) ? (start - WARM) : 0;

        float cp = 0.0f, dp = 0.0f;
        float t_i = st[SKW(wstart)];
        float y_i = sy[SKW(wstart)];
        float idt_m = 0.0f, dy_m = 0.0f;
        if (wstart > 0) {
            idt_m = 1.0f / (t_i - st[SKW(wstart - 1)]);
            dy_m  = y_i - sy[SKW(wstart - 1)];
        }

        for (int i = wstart; i < start + CHUNK; ++i) {
            float idt_p = 0.0f, dy_p = 0.0f;
            float t_ip1 = t_i, y_ip1 = y_i;
            if (i < N_KNOTS - 1) {
                t_ip1 = st[SKW(i + 1)];
                y_ip1 = sy[SKW(i + 1)];
                idt_p = 1.0f / (t_ip1 - t_i);
                dy_p  = y_ip1 - y_i;
            }
            float l, m, u, b;
            if (i == 0) {
                l = 0.0f; m = 2.0f * idt_p; u = idt_p;
                b = 3.0f * dy_p * idt_p * idt_p;
            } else if (i == N_KNOTS - 1) {
                l = idt_m; m = 2.0f * idt_m; u = 0.0f;
                b = 3.0f * dy_m * idt_m * idt_m;
            } else {
                l = idt_m; m = 2.0f * (idt_m + idt_p); u = idt_p;
                b = 3.0f * (dy_m * idt_m * idt_m + dy_p * idt_p * idt_p);
            }
            float inv = 1.0f / (m - l * cp);
            cp = u * inv;
            dp = (b - l * dp) * inv;
            if (i >= start) {
                sc[SKW(i)] = cp;
                sd[SKW(i)] = dp;
            }
            idt_m = idt_p; dy_m = dy_p; t_i = t_ip1; y_i = y_ip1;
        }
    }
    __syncthreads();

    // ---------------- backward substitution (chunked, warmup) ---------
    float xloc[CHUNK];
    {
        const int start = tid * CHUNK;
        float x = 0.0f;
        int wtop = start + CHUNK + WARM;
        if (wtop > N_KNOTS) wtop = N_KNOTS;
        for (int i = wtop - 1; i >= start + CHUNK; --i)
            x = sd[SKW(i)] - sc[SKW(i)] * x;
        #pragma unroll
        for (int j = CHUNK - 1; j >= 0; --j) {
            int i = start + j;
            x = sd[SKW(i)] - sc[SKW(i)] * x;
            xloc[j] = x;
        }
    }
    __syncthreads();
    {
        const int start = tid * CHUNK;
        #pragma unroll
        for (int j = 0; j < CHUNK; ++j) sd[SKW(start + j)] = xloc[j];
    }
    __syncthreads();

    // ---------------- query evaluation ----------------
    const float tmin = st[SKW(0)];
    const float tmax = st[SKW(N_KNOTS - 1)];
    const float scale = (float)(N_KNOTS - 1) / (tmax - tmin);

    const float4* tqg4 = (const float4*)(tq_g + (size_t)row * QPTS);
    float4* outg4      = (float4*)(out_g + (size_t)row * QPTS);

    #pragma unroll
    for (int v = tid; v < QPTS / 4; v += THREADS) {
        float4 tq4 = tqg4[v];
        float r[4];
        #pragma unroll
        for (int e = 0; e < 4; ++e) {
            const float tq = (e == 0) ? tq4.x : (e == 1) ? tq4.y
                           : (e == 2) ? tq4.z : tq4.w;

            // interpolation guess + windowed binary search
            int g = (int)((tq - tmin) * scale);
            g = (g < 0) ? 0 : (g > N_KNOTS - 2 ? N_KNOTS - 2 : g);
            int lo = g - 48; if (lo < 0) lo = 0;
            int hi = g + 48; if (hi > N_KNOTS - 1) hi = N_KNOTS - 1;
            if (!(st[SKW(lo)] <= tq && tq < st[SKW(hi)])) {
                lo = 0; hi = N_KNOTS - 1;   // fallback: essentially never taken
                #pragma unroll
                for (int it = 0; it < 5; ++it) {
                    int mid = (lo + hi) >> 1;
                    if (st[SKW(mid)] <= tq) lo = mid; else hi = mid;
                }
            }
            #pragma unroll
            for (int it = 0; it < 7; ++it) {
                int mid = (lo + hi) >> 1;
                if (st[SKW(mid)] <= tq) lo = mid; else hi = mid;
            }
            int idx = (lo > N_KNOTS - 2) ? N_KNOTS - 2 : lo;

            const int pi = SKW(idx), pj = SKW(idx + 1);
            const float t0 = st[pi], t1 = st[pj];
            const float y0 = sy[pi], y1 = sy[pj];
            const float d0 = sd[pi], d1 = sd[pj];
            const float dt = t1 - t0;
            const float s  = (tq - t0) / dt;

            const float c1 = y0 + d0 * dt * (1.0f / 3.0f);
            const float c2 = y1 - d1 * dt * (1.0f / 3.0f);
            const float p1 = 3.0f * (c1 - y0);
            const float p2 = 3.0f * (y0 - 2.0f * c1 + c2);
            const float p3 = -y0 + 3.0f * c1 - 3.0f * c2 + y1;

            r[e] = ((p3 * s + p2) * s + p1) * s + y0;
        }
        outg4[v] = make_float4(r[0], r[1], r[2], r[3]);
    }
}

extern "C" void kernel_launch(void* const* d_in, const int* in_sizes, int n_in,
                              void* d_out, int out_size)
{
    const float* t  = (const float*)d_in[0];
    const float* y  = (const float*)d_in[1];
    const float* tq = (const float*)d_in[2];
    float* out = (float*)d_out;

    const int rows = out_size / QPTS;                 // 2048
    const int smem = 4 * ASZ * sizeof(float);         // 69632 B

    cudaFuncSetAttribute(spline_kernel,
                         cudaFuncAttributeMaxDynamicSharedMemorySize, smem);

    spline_kernel<<<rows, THREADS, smem>>>(t, y, tq, out);
}

// round 4
// speedup vs baseline: 4.1675x; 1.5575x over previous
#include <cuda_runtime.h>
#include <cuda_bf16.h>
#include <math.h>

// Spline_2817498546198 — R4
// One CTA per row (2048 rows, N=4096 knots, Q=2048 queries).
// Chunked Thomas with 16-step warmup (contraction factor <= 0.5/step),
// skewed conflict-free smem, fast-div intrinsics, branch-free inner loop,
// interpolation-guessed windowed binary search.

#define N_KNOTS 4096
#define QPTS    2048
#define CHUNK   16
#define WARM    16
#define THREADS 256
#define SKW(i)  ((i) + ((i) >> 4))
#define ASZ     (N_KNOTS + (N_KNOTS >> 4))   // 4352 floats per array

__global__ __launch_bounds__(THREADS, 3)
void spline_kernel(const float* __restrict__ t_g,
                   const float* __restrict__ y_g,
                   const float* __restrict__ tq_g,
                   float* __restrict__ out_g)
{
    extern __shared__ float sm[];
    float* st = sm;            // t   (skewed)
    float* sy = sm + ASZ;      // y   (skewed)
    float* sc = sm + 2 * ASZ;  // c   (skewed)
    float* sd = sm + 3 * ASZ;  // d -> x (skewed)

    const int row = blockIdx.x;
    const int tid = threadIdx.x;

    // ---- load t, y into skewed smem ----
    const float4* tg4 = (const float4*)(t_g + (size_t)row * N_KNOTS);
    const float4* yg4 = (const float4*)(y_g + (size_t)row * N_KNOTS);
    #pragma unroll
    for (int v = tid; v < N_KNOTS / 4; v += THREADS) {
        float4 tv = tg4[v];
        float4 yv = yg4[v];
        int p = SKW(v * 4);        // 4 consecutive stay in same 16-block
        st[p] = tv.x; st[p + 1] = tv.y; st[p + 2] = tv.z; st[p + 3] = tv.w;
        sy[p] = yv.x; sy[p + 1] = yv.y; sy[p + 2] = yv.z; sy[p + 3] = yv.w;
    }
    __syncthreads();

    // ---------------- forward Thomas (chunked, warmup) ----------------
    {
        const int start  = tid * CHUNK;
        const int wstart = (start >= WARM) ? (start - WARM) : 0;

        float cp = 0.0f, dp = 0.0f;
        float t_i = st[SKW(wstart)];
        float y_i = sy[SKW(wstart)];
        float idt_m = 0.0f, dy_m = 0.0f;
        if (wstart > 0) {
            idt_m = __fdividef(1.0f, t_i - st[SKW(wstart - 1)]);
            dy_m  = y_i - sy[SKW(wstart - 1)];
        }

        for (int i = wstart; i < start + CHUNK; ++i) {
            // boundary rows are the interior formula with idt = 0
            float idt_p = 0.0f, dy_p = 0.0f;
            float t_ip1 = t_i, y_ip1 = y_i;
            if (i < N_KNOTS - 1) {
                t_ip1 = st[SKW(i + 1)];
                y_ip1 = sy[SKW(i + 1)];
                idt_p = __fdividef(1.0f, t_ip1 - t_i);
                dy_p  = y_ip1 - y_i;
            }
            const float m = 2.0f * (idt_m + idt_p);
            const float b = 3.0f * (dy_m * idt_m * idt_m + dy_p * idt_p * idt_p);
            const float inv = __fdividef(1.0f, m - idt_m * cp);
            cp = idt_p * inv;
            dp = (b - idt_m * dp) * inv;
            if (i >= start) {
                sc[SKW(i)] = cp;
                sd[SKW(i)] = dp;
            }
            idt_m = idt_p; dy_m = dy_p; t_i = t_ip1; y_i = y_ip1;
        }
    }
    __syncthreads();

    // ---------------- backward substitution (chunked, warmup) ---------
    float xloc[CHUNK];
    {
        const int start = tid * CHUNK;
        float x = 0.0f;
        int wtop = start + CHUNK + WARM;
        if (wtop > N_KNOTS) wtop = N_KNOTS;
        for (int i = wtop - 1; i >= start + CHUNK; --i)
            x = sd[SKW(i)] - sc[SKW(i)] * x;
        #pragma unroll
        for (int j = CHUNK - 1; j >= 0; --j) {
            int i = start + j;
            x = sd[SKW(i)] - sc[SKW(i)] * x;
            xloc[j] = x;
        }
    }
    __syncthreads();
    {
        const int start = tid * CHUNK;
        #pragma unroll
        for (int j = 0; j < CHUNK; ++j) sd[SKW(start + j)] = xloc[j];
    }
    __syncthreads();

    // ---------------- query evaluation ----------------
    const float tmin = st[SKW(0)];
    const float tmax = st[SKW(N_KNOTS - 1)];
    const float scale = (float)(N_KNOTS - 1) / (tmax - tmin);

    const float4* tqg4 = (const float4*)(tq_g + (size_t)row * QPTS);
    float4* outg4      = (float4*)(out_g + (size_t)row * QPTS);

    #pragma unroll
    for (int v = tid; v < QPTS / 4; v += THREADS) {
        float4 tq4 = tqg4[v];
        float r[4];
        #pragma unroll
        for (int e = 0; e < 4; ++e) {
            const float tq = (e == 0) ? tq4.x : (e == 1) ? tq4.y
                           : (e == 2) ? tq4.z : tq4.w;

            // interpolation guess + windowed binary search
            int g = (int)((tq - tmin) * scale);
            g = (g < 0) ? 0 : (g > N_KNOTS - 2 ? N_KNOTS - 2 : g);
            int lo = g - 48; if (lo < 0) lo = 0;
            int hi = g + 48; if (hi > N_KNOTS - 1) hi = N_KNOTS - 1;
            if (!(st[SKW(lo)] <= tq && tq < st[SKW(hi)])) {
                lo = 0; hi = N_KNOTS - 1;   // fallback: essentially never taken
                #pragma unroll
                for (int it = 0; it < 5; ++it) {
                    int mid = (lo + hi) >> 1;
                    if (st[SKW(mid)] <= tq) lo = mid; else hi = mid;
                }
            }
            #pragma unroll
            for (int it = 0; it < 7; ++it) {
                int mid = (lo + hi) >> 1;
                if (st[SKW(mid)] <= tq) lo = mid; else hi = mid;
            }
            int idx = (lo > N_KNOTS - 2) ? N_KNOTS - 2 : lo;

            const int pi = SKW(idx), pj = SKW(idx + 1);
            const float t0 = st[pi], t1 = st[pj];
            const float y0 = sy[pi], y1 = sy[pj];
            const float d0 = sd[pi], d1 = sd[pj];
            const float dt = t1 - t0;
            const float s  = __fdividef(tq - t0, dt);

            const float c1 = y0 + d0 * dt * (1.0f / 3.0f);
            const float c2 = y1 - d1 * dt * (1.0f / 3.0f);
            const float p1 = 3.0f * (c1 - y0);
            const float p2 = 3.0f * (y0 - 2.0f * c1 + c2);
            const float p3 = -y0 + 3.0f * c1 - 3.0f * c2 + y1;

            r[e] = ((p3 * s + p2) * s + p1) * s + y0;
        }
        outg4[v] = make_float4(r[0], r[1], r[2], r[3]);
    }
}

extern "C" void kernel_launch(void* const* d_in, const int* in_sizes, int n_in,
                              void* d_out, int out_size)
{
    const float* t  = (const float*)d_in[0];
    const float* y  = (const float*)d_in[1];
    const float* tq = (const float*)d_in[2];
    float* out = (float*)d_out;

    const int rows = out_size / QPTS;                 // 2048
    const int smem = 4 * ASZ * sizeof(float);         // 69632 B

    cudaFuncSetAttribute(spline_kernel,
                         cudaFuncAttributeMaxDynamicSharedMemorySize, smem);

    spline_kernel<<<rows, THREADS, smem>>>(t, y, tq, out);
}